// round 3
// baseline (speedup 1.0000x reference)
#include <cuda_runtime.h>
#include <math.h>
#include <stdint.h>

#define B_ 8
#define N_ 1024
#define C_ 768
#define H_ 12
#define D_ 64
#define BH_ (B_*H_)

// Scratch (device globals — no allocation allowed)
__device__ float g_q [BH_*N_*D_];   // [B,H,N,D] (LayerNorm'd, q also *SCALE)
__device__ float g_k [BH_*N_*D_];
__device__ float g_v [BH_*N_*D_];
__device__ float g_ao[B_*N_*C_];    // attention output in [B,N,C]

// ---------------------------------------------------------------------------
// tf32 helpers
// ---------------------------------------------------------------------------
__device__ __forceinline__ uint32_t f2tf(float f) {
    uint32_t u;
    asm("cvt.rna.tf32.f32 %0, %1;" : "=r"(u) : "f"(f));
    return u;
}

__device__ __forceinline__ void mma8(float* c, const uint32_t* a, const uint32_t* b) {
    asm volatile(
        "mma.sync.aligned.m16n8k8.row.col.f32.tf32.tf32.f32 "
        "{%0,%1,%2,%3},{%4,%5,%6,%7},{%8,%9},{%0,%1,%2,%3};"
        : "+f"(c[0]), "+f"(c[1]), "+f"(c[2]), "+f"(c[3])
        : "r"(a[0]), "r"(a[1]), "r"(a[2]), "r"(a[3]), "r"(b[0]), "r"(b[1]));
}

// Paired-column swizzled smem addressing.
// 16-float rows (GEMM): 8 uint2 slots/row. slot s holds cols (kk*8+pos, +4), s=kk*4+pos.
__device__ __forceinline__ int sw16(int r, int s) {
    return r*8 + (s ^ (((r&2)<<1) ^ ((r>>2)&3)));
}
// 64-float rows (flash): 32 uint2 slots/row. slot s = kf*4+pos holds cols (kf*8+pos, +4).
__device__ __forceinline__ int sw64(int r, int s) {
    return r*32 + (s ^ (((r&3)<<2) ^ ((r>>2)&3) ^ (((s>>4)&1)<<1)));
}

// ---------------------------------------------------------------------------
// tf32 GEMM: Y[m,c] = sum_k A[m,k] * W[c,k]
// Block 128x128, BK=16, 128 threads = 4 warps (2x2), warp tile 64x64.
// Smem holds pre-converted tf32 bits in paired-swizzled layout (LDS.64 frags).
// MODE 0: fused per-head LayerNorm epilogue, scatter into g_q/g_k/g_v.
// MODE 1: A := g_ao, plain row-major store.
// ---------------------------------------------------------------------------
template<int MODE>
__global__ __launch_bounds__(128)
void gemm_tf32(const float* __restrict__ A, const float* __restrict__ W,
               float* __restrict__ Y, int M, int Ncol, int K)
{
    __shared__ uint2 As2[128*8];
    __shared__ uint2 Ws2[128*8];

    const int tid  = threadIdx.x;
    const int warp = tid >> 5, lane = tid & 31;
    const int g    = lane >> 2, tig = lane & 3;
    const int wm   = (warp >> 1) * 64;
    const int wn   = (warp & 1)  * 64;
    const int bm   = blockIdx.y * 128;
    const int bn   = blockIdx.x * 128;

    if (MODE == 1) A = g_ao;

    const float* Ap = A + (size_t)(bm + tid) * K;   // one row per thread
    const float* Wp = W + (size_t)(bn + tid) * K;

    float acc[4][8][4];
    #pragma unroll
    for (int i = 0; i < 4; i++)
        #pragma unroll
        for (int j = 0; j < 8; j++)
            #pragma unroll
            for (int e = 0; e < 4; e++) acc[i][j][e] = 0.f;

    float4 ra[4], rw[4];
    #pragma unroll
    for (int q = 0; q < 4; q++) {
        ra[q] = *(const float4*)(Ap + q*4);
        rw[q] = *(const float4*)(Wp + q*4);
    }

    for (int k0 = 0; k0 < K; k0 += 16) {
        __syncthreads();
        {
            const float* va = (const float*)ra;
            const float* vw = (const float*)rw;
            #pragma unroll
            for (int kk = 0; kk < 2; kk++)
                #pragma unroll
                for (int pos = 0; pos < 4; pos++) {
                    As2[sw16(tid, kk*4+pos)] =
                        make_uint2(f2tf(va[kk*8+pos]), f2tf(va[kk*8+pos+4]));
                    Ws2[sw16(tid, kk*4+pos)] =
                        make_uint2(f2tf(vw[kk*8+pos]), f2tf(vw[kk*8+pos+4]));
                }
        }
        __syncthreads();

        if (k0 + 16 < K) {
            Ap += 16; Wp += 16;
            #pragma unroll
            for (int q = 0; q < 4; q++) {
                ra[q] = *(const float4*)(Ap + q*4);
                rw[q] = *(const float4*)(Wp + q*4);
            }
        }

        #pragma unroll
        for (int kk = 0; kk < 2; kk++) {
            uint32_t af[4][4];
            #pragma unroll
            for (int mf = 0; mf < 4; mf++) {
                const int rA = wm + mf*16 + g;
                uint2 lo = As2[sw16(rA,     kk*4 + tig)];
                uint2 hi = As2[sw16(rA + 8, kk*4 + tig)];
                af[mf][0] = lo.x; af[mf][1] = hi.x;
                af[mf][2] = lo.y; af[mf][3] = hi.y;
            }
            uint32_t bf[8][2];
            #pragma unroll
            for (int nf = 0; nf < 8; nf++) {
                uint2 bb = Ws2[sw16(wn + nf*8 + g, kk*4 + tig)];
                bf[nf][0] = bb.x; bf[nf][1] = bb.y;
            }
            #pragma unroll
            for (int mf = 0; mf < 4; mf++)
                #pragma unroll
                for (int nf = 0; nf < 8; nf++)
                    mma8(acc[mf][nf], af[mf], bf[nf]);
        }
    }

    // ---- epilogue ----
    const int cbase = bn + wn;           // warp col window start (mult of 64)
    if (MODE == 1) {
        #pragma unroll
        for (int mf = 0; mf < 4; mf++) {
            const int m0 = bm + wm + mf*16 + g;
            #pragma unroll
            for (int nf = 0; nf < 8; nf++) {
                const int c = cbase + nf*8 + 2*tig;
                float2 v0; v0.x = acc[mf][nf][0]; v0.y = acc[mf][nf][1];
                float2 v1; v1.x = acc[mf][nf][2]; v1.y = acc[mf][nf][3];
                *(float2*)&Y[(size_t)m0      * Ncol + c] = v0;
                *(float2*)&Y[(size_t)(m0+8) * Ncol + c] = v1;
            }
        }
        return;
    }

    // MODE 0: warp covers exactly one (s, head) slice of 64 cols.
    const int s_sel = cbase / C_;
    const int h     = (cbase - s_sel*C_) >> 6;
    float* buf = (s_sel == 0) ? g_q : ((s_sel == 1) ? g_k : g_v);
    const float scl = (s_sel == 0) ? 0.125f : 1.0f;

    #pragma unroll
    for (int mf = 0; mf < 4; mf++) {
        const int m0 = bm + wm + mf*16 + g;   // rows m0, m0+8
        if (s_sel <= 1) {
            // LayerNorm over the 64 cols of each row
            float sA = 0.f, sB = 0.f;
            #pragma unroll
            for (int nf = 0; nf < 8; nf++) {
                sA += acc[mf][nf][0] + acc[mf][nf][1];
                sB += acc[mf][nf][2] + acc[mf][nf][3];
            }
            sA += __shfl_xor_sync(0xffffffffu, sA, 1);
            sA += __shfl_xor_sync(0xffffffffu, sA, 2);
            sB += __shfl_xor_sync(0xffffffffu, sB, 1);
            sB += __shfl_xor_sync(0xffffffffu, sB, 2);
            const float mA = sA * (1.0f/64.0f);
            const float mB = sB * (1.0f/64.0f);
            float vA = 0.f, vB = 0.f;
            #pragma unroll
            for (int nf = 0; nf < 8; nf++) {
                acc[mf][nf][0] -= mA; acc[mf][nf][1] -= mA;
                acc[mf][nf][2] -= mB; acc[mf][nf][3] -= mB;
                vA += acc[mf][nf][0]*acc[mf][nf][0] + acc[mf][nf][1]*acc[mf][nf][1];
                vB += acc[mf][nf][2]*acc[mf][nf][2] + acc[mf][nf][3]*acc[mf][nf][3];
            }
            vA += __shfl_xor_sync(0xffffffffu, vA, 1);
            vA += __shfl_xor_sync(0xffffffffu, vA, 2);
            vB += __shfl_xor_sync(0xffffffffu, vB, 1);
            vB += __shfl_xor_sync(0xffffffffu, vB, 2);
            const float iA = rsqrtf(vA * (1.0f/64.0f) + 1e-5f) * scl;
            const float iB = rsqrtf(vB * (1.0f/64.0f) + 1e-5f) * scl;
            #pragma unroll
            for (int nf = 0; nf < 8; nf++) {
                acc[mf][nf][0] *= iA; acc[mf][nf][1] *= iA;
                acc[mf][nf][2] *= iB; acc[mf][nf][3] *= iB;
            }
        }
        const int b0 = m0 >> 10, n0 = m0 & 1023;
        const int b1 = (m0+8) >> 10, n1 = (m0+8) & 1023;
        #pragma unroll
        for (int nf = 0; nf < 8; nf++) {
            const int d = nf*8 + 2*tig;
            float2 v0; v0.x = acc[mf][nf][0]; v0.y = acc[mf][nf][1];
            float2 v1; v1.x = acc[mf][nf][2]; v1.y = acc[mf][nf][3];
            *(float2*)&buf[(((size_t)b0*H_ + h)*N_ + n0)*D_ + d] = v0;
            *(float2*)&buf[(((size_t)b1*H_ + h)*N_ + n1)*D_ + d] = v1;
        }
    }
}

// ---------------------------------------------------------------------------
// Flash attention, tf32 mma, pre-converted swizzled K / V^T tiles.
// One block = 64 q rows of one (b,h), 128 threads = 4 warps (16 q rows each).
// ---------------------------------------------------------------------------
#define FPT 68

__global__ __launch_bounds__(128)
void flash_tf32()
{
    extern __shared__ char smemraw[];
    uint2* Ks2 = (uint2*)smemraw;            // 64 rows x 32 uint2  (16KB)
    uint2* Vt2 = Ks2 + 64*32;                // 16KB (V^T: row=d, col=key)
    float* ps  = (float*)(Vt2 + 64*32);      // [64][FPT] P (also Q at start)
    float* qs  = ps;

    const int bh    = blockIdx.y;
    const int qtile = blockIdx.x;
    const int b = bh / H_;
    const int h = bh - b * H_;

    const float* Q  = g_q + (size_t)bh * N_ * D_ + (size_t)qtile * 64 * D_;
    const float* Kp = g_k + (size_t)bh * N_ * D_;
    const float* Vp = g_v + (size_t)bh * N_ * D_;

    const int tid  = threadIdx.x;
    const int warp = tid >> 5, lane = tid & 31;
    const int g    = lane >> 2, tig = lane & 3;
    const int wband = warp * 16;

    // load q tile into qs (pitch FPT)
    for (int i = tid; i < 64*16; i += 128) {
        const int r = i >> 4, cv = (i & 15) << 2;
        *(float4*)&qs[r*FPT + cv] = *(const float4*)(Q + r*64 + cv);
    }
    __syncthreads();

    // hoist Q A-frags (tf32) — reused for all 16 KV tiles
    uint32_t qa[8][4];
    #pragma unroll
    for (int kf = 0; kf < 8; kf++) {
        const int r0 = wband + g;
        qa[kf][0] = f2tf(qs[ r0     *FPT + kf*8 + tig]);
        qa[kf][1] = f2tf(qs[(r0 + 8)*FPT + kf*8 + tig]);
        qa[kf][2] = f2tf(qs[ r0     *FPT + kf*8 + tig + 4]);
        qa[kf][3] = f2tf(qs[(r0 + 8)*FPT + kf*8 + tig + 4]);
    }

    float o[8][4];
    #pragma unroll
    for (int nf = 0; nf < 8; nf++)
        #pragma unroll
        for (int e = 0; e < 4; e++) o[nf][e] = 0.f;
    float m0 = -1e30f, m1 = -1e30f, l0 = 0.f, l1 = 0.f;

    // K loader mapping: row = tid&63, half = tid>>6 (conflict-free swizzled stores)
    const int krow = tid & 63, khalf = tid >> 6;
    // V loader mapping: key = tid>>1, d-half = (tid&1)*32
    const int vkey = tid >> 1, vdh = (tid & 1) * 32;
    const int vs_slot = (vkey >> 3)*4 + (vkey & 3);
    const int vs_half = (vkey >> 2) & 1;

    for (int j = 0; j < 16; j++) {
        __syncthreads();  // prior iter done reading Ks2/Vt2 (and tile0: qa hoisted)

        // K tile -> tf32 paired swizzled
        {
            const float* Kg = Kp + (size_t)j*4096 + krow*64 + khalf*32;
            float kv[32];
            #pragma unroll
            for (int q = 0; q < 8; q++)
                *(float4*)&kv[q*4] = *(const float4*)(Kg + q*4);
            #pragma unroll
            for (int kfi = 0; kfi < 4; kfi++) {
                const int kf = khalf*4 + kfi;
                #pragma unroll
                for (int pos = 0; pos < 4; pos++)
                    Ks2[sw64(krow, kf*4+pos)] =
                        make_uint2(f2tf(kv[kfi*8+pos]), f2tf(kv[kfi*8+pos+4]));
            }
        }
        // V tile -> transposed tf32 paired swizzled (row=d, col=key)
        {
            const float* Vg = Vp + (size_t)j*4096 + vkey*64 + vdh;
            uint32_t* Vt32 = (uint32_t*)Vt2;
            #pragma unroll
            for (int q = 0; q < 8; q++) {
                float4 v4 = *(const float4*)(Vg + q*4);
                const int d0 = vdh + q*4;
                Vt32[sw64(d0+0, vs_slot)*2 + vs_half] = f2tf(v4.x);
                Vt32[sw64(d0+1, vs_slot)*2 + vs_half] = f2tf(v4.y);
                Vt32[sw64(d0+2, vs_slot)*2 + vs_half] = f2tf(v4.z);
                Vt32[sw64(d0+3, vs_slot)*2 + vs_half] = f2tf(v4.w);
            }
        }
        __syncthreads();

        // S = Q @ K^T   (warp: 16 rows x 64 cols)
        float s[8][4];
        #pragma unroll
        for (int nf = 0; nf < 8; nf++)
            #pragma unroll
            for (int e = 0; e < 4; e++) s[nf][e] = 0.f;

        #pragma unroll
        for (int kf = 0; kf < 8; kf++)
            #pragma unroll
            for (int nf = 0; nf < 8; nf++) {
                uint2 bb = Ks2[sw64(nf*8 + g, kf*4 + tig)];
                uint32_t bfr[2] = {bb.x, bb.y};
                mma8(s[nf], qa[kf], bfr);
            }

        // online softmax
        float mx0 = -1e30f, mx1 = -1e30f;
        #pragma unroll
        for (int nf = 0; nf < 8; nf++) {
            mx0 = fmaxf(mx0, fmaxf(s[nf][0], s[nf][1]));
            mx1 = fmaxf(mx1, fmaxf(s[nf][2], s[nf][3]));
        }
        mx0 = fmaxf(mx0, __shfl_xor_sync(0xffffffffu, mx0, 1));
        mx0 = fmaxf(mx0, __shfl_xor_sync(0xffffffffu, mx0, 2));
        mx1 = fmaxf(mx1, __shfl_xor_sync(0xffffffffu, mx1, 1));
        mx1 = fmaxf(mx1, __shfl_xor_sync(0xffffffffu, mx1, 2));

        const float mn0 = fmaxf(m0, mx0);
        const float mn1 = fmaxf(m1, mx1);
        const float corr0 = __expf(m0 - mn0);
        const float corr1 = __expf(m1 - mn1);
        m0 = mn0; m1 = mn1;

        float rs0 = 0.f, rs1 = 0.f;
        #pragma unroll
        for (int nf = 0; nf < 8; nf++) {
            const float p0 = __expf(s[nf][0] - mn0);
            const float p1 = __expf(s[nf][1] - mn0);
            const float p2 = __expf(s[nf][2] - mn1);
            const float p3 = __expf(s[nf][3] - mn1);
            rs0 += p0 + p1;
            rs1 += p2 + p3;
            float2 w0; w0.x = p0; w0.y = p1;
            float2 w1; w1.x = p2; w1.y = p3;
            *(float2*)&ps[(wband + g    )*FPT + nf*8 + 2*tig] = w0;
            *(float2*)&ps[(wband + g + 8)*FPT + nf*8 + 2*tig] = w1;
        }
        rs0 += __shfl_xor_sync(0xffffffffu, rs0, 1);
        rs0 += __shfl_xor_sync(0xffffffffu, rs0, 2);
        rs1 += __shfl_xor_sync(0xffffffffu, rs1, 1);
        rs1 += __shfl_xor_sync(0xffffffffu, rs1, 2);
        l0 = l0 * corr0 + rs0;
        l1 = l1 * corr1 + rs1;

        #pragma unroll
        for (int nf = 0; nf < 8; nf++) {
            o[nf][0] *= corr0; o[nf][1] *= corr0;
            o[nf][2] *= corr1; o[nf][3] *= corr1;
        }
        __syncwarp();

        // O += P @ V
        #pragma unroll
        for (int kf = 0; kf < 8; kf++) {
            uint32_t pa[4];
            pa[0] = f2tf(ps[(wband + g    )*FPT + kf*8 + tig]);
            pa[1] = f2tf(ps[(wband + g + 8)*FPT + kf*8 + tig]);
            pa[2] = f2tf(ps[(wband + g    )*FPT + kf*8 + tig + 4]);
            pa[3] = f2tf(ps[(wband + g + 8)*FPT + kf*8 + tig + 4]);
            #pragma unroll
            for (int nf = 0; nf < 8; nf++) {
                uint2 bb = Vt2[sw64(nf*8 + g, kf*4 + tig)];
                uint32_t bv[2] = {bb.x, bb.y};
                mma8(o[nf], pa, bv);
            }
        }
        __syncwarp();
    }

    // epilogue: O / l  -> g_ao [B,N,C], c = h*64 + d
    const float inv0 = 1.0f / l0;
    const float inv1 = 1.0f / l1;
    const int n0 = qtile*64 + wband + g;
    const int n1 = n0 + 8;
    #pragma unroll
    for (int nf = 0; nf < 8; nf++) {
        const int d = h*64 + nf*8 + 2*tig;
        float2 w0; w0.x = o[nf][0]*inv0; w0.y = o[nf][1]*inv0;
        float2 w1; w1.x = o[nf][2]*inv1; w1.y = o[nf][3]*inv1;
        *(float2*)&g_ao[((size_t)b*N_ + n0)*C_ + d] = w0;
        *(float2*)&g_ao[((size_t)b*N_ + n1)*C_ + d] = w1;
    }
}

// ---------------------------------------------------------------------------
extern "C" void kernel_launch(void* const* d_in, const int* in_sizes, int n_in,
                              void* d_out, int out_size)
{
    const float* x     = (const float*)d_in[0];   // [B,N,C]
    const float* wqkv  = (const float*)d_in[1];   // [3C,C]
    const float* wproj = (const float*)d_in[2];   // [C,C]
    float* out = (float*)d_out;                   // [B,N,C]

    // 1) QKV GEMM + fused per-head LayerNorm -> q/k/v [B,H,N,D]
    {
        dim3 grid(3*C_/128, (B_*N_)/128);   // (18, 64)
        gemm_tf32<0><<<grid, 128>>>(x, wqkv, nullptr, B_*N_, 3*C_, C_);
    }

    // 2) Flash attention -> g_ao
    {
        const int smem_bytes = 2*64*32*(int)sizeof(uint2) + 64*FPT*(int)sizeof(float);
        cudaFuncSetAttribute(flash_tf32,
                             cudaFuncAttributeMaxDynamicSharedMemorySize, smem_bytes);
        dim3 grid(N_/64, BH_);   // (16, 96)
        flash_tf32<<<grid, 128, smem_bytes>>>();
    }

    // 3) Output projection
    {
        dim3 grid(C_/128, (B_*N_)/128);     // (6, 64)
        gemm_tf32<1><<<grid, 128>>>(nullptr, wproj, out, B_*N_, C_, C_);
    }
}

// round 4
// speedup vs baseline: 1.4691x; 1.4691x over previous
#include <cuda_runtime.h>
#include <math.h>
#include <stdint.h>

#define B_ 8
#define N_ 1024
#define C_ 768
#define H_ 12
#define D_ 64
#define BH_ (B_*H_)

// Scratch (device globals — no allocation allowed)
__device__ float g_q [BH_*N_*D_];   // [B,H,N,D]
__device__ float g_k [BH_*N_*D_];
__device__ float g_v [BH_*N_*D_];
__device__ float g_ao[B_*N_*C_];    // attention output in [B,N,C]

// ---------------------------------------------------------------------------
// tf32 helpers
// ---------------------------------------------------------------------------
__device__ __forceinline__ uint32_t f2tf(float f) {
    uint32_t u;
    asm("cvt.rna.tf32.f32 %0, %1;" : "=r"(u) : "f"(f));
    return u;
}

__device__ __forceinline__ void mma8(float* c, const uint32_t* a, const uint32_t* b) {
    asm volatile(
        "mma.sync.aligned.m16n8k8.row.col.f32.tf32.tf32.f32 "
        "{%0,%1,%2,%3},{%4,%5,%6,%7},{%8,%9},{%0,%1,%2,%3};"
        : "+f"(c[0]), "+f"(c[1]), "+f"(c[2]), "+f"(c[3])
        : "r"(a[0]), "r"(a[1]), "r"(a[2]), "r"(a[3]), "r"(b[0]), "r"(b[1]));
}

// Paired-column swizzled smem addressing: 8 uint2 slots per 16-float row.
// Slot s = kk*4+pos holds tf32 bits of cols (kk*8+pos, kk*8+pos+4).
__device__ __forceinline__ int sw16(int r, int s) {
    return r*8 + (s ^ (((r&2)<<1) ^ ((r>>2)&3)));
}

// ---------------------------------------------------------------------------
// tf32 GEMM: Y[m,c] = sum_k A[m,k] * W[c,k]
// Block 128x128, BK=16, 256 threads = 8 warps (2x4), warp tile 64x32.
// Smem: pre-converted tf32 bits, paired-swizzled (LDS.64 fragments).
// MODE 0: scatter into g_q/g_k/g_v;  MODE 1: A := g_ao, row-major store.
// ---------------------------------------------------------------------------
template<int MODE>
__global__ __launch_bounds__(256)
void gemm_tf32(const float* __restrict__ A, const float* __restrict__ W,
               float* __restrict__ Y, int M, int Ncol, int K)
{
    __shared__ uint2 As2[128*8];
    __shared__ uint2 Ws2[128*8];

    const int tid  = threadIdx.x;
    const int warp = tid >> 5, lane = tid & 31;
    const int g    = lane >> 2, tig = lane & 3;
    const int wm   = (warp >> 2) * 64;
    const int wn   = (warp & 3)  * 32;
    const int bm   = blockIdx.y * 128;
    const int bn   = blockIdx.x * 128;

    if (MODE == 1) A = g_ao;

    const int lrow  = tid & 127;
    const int lhalf = tid >> 7;          // 0: cols 0-7, 1: cols 8-15

    const float* Ap = A + (size_t)(bm + lrow) * K + lhalf*8;
    const float* Wp = W + (size_t)(bn + lrow) * K + lhalf*8;

    float acc[4][4][4];
    #pragma unroll
    for (int i = 0; i < 4; i++)
        #pragma unroll
        for (int j = 0; j < 4; j++)
            #pragma unroll
            for (int e = 0; e < 4; e++) acc[i][j][e] = 0.f;

    float va[8], vw[8];
    *(float4*)&va[0] = *(const float4*)Ap;
    *(float4*)&va[4] = *(const float4*)(Ap + 4);
    *(float4*)&vw[0] = *(const float4*)Wp;
    *(float4*)&vw[4] = *(const float4*)(Wp + 4);

    for (int k0 = 0; k0 < K; k0 += 16) {
        __syncthreads();
        #pragma unroll
        for (int pos = 0; pos < 4; pos++) {
            As2[sw16(lrow, lhalf*4 + pos)] =
                make_uint2(f2tf(va[pos]), f2tf(va[pos+4]));
            Ws2[sw16(lrow, lhalf*4 + pos)] =
                make_uint2(f2tf(vw[pos]), f2tf(vw[pos+4]));
        }
        __syncthreads();

        if (k0 + 16 < K) {
            Ap += 16; Wp += 16;
            *(float4*)&va[0] = *(const float4*)Ap;
            *(float4*)&va[4] = *(const float4*)(Ap + 4);
            *(float4*)&vw[0] = *(const float4*)Wp;
            *(float4*)&vw[4] = *(const float4*)(Wp + 4);
        }

        #pragma unroll
        for (int kk = 0; kk < 2; kk++) {
            uint32_t af[4][4];
            #pragma unroll
            for (int mf = 0; mf < 4; mf++) {
                const int rA = wm + mf*16 + g;
                uint2 lo = As2[sw16(rA,     kk*4 + tig)];
                uint2 hi = As2[sw16(rA + 8, kk*4 + tig)];
                af[mf][0] = lo.x; af[mf][1] = hi.x;
                af[mf][2] = lo.y; af[mf][3] = hi.y;
            }
            uint32_t bf[4][2];
            #pragma unroll
            for (int nf = 0; nf < 4; nf++) {
                uint2 bb = Ws2[sw16(wn + nf*8 + g, kk*4 + tig)];
                bf[nf][0] = bb.x; bf[nf][1] = bb.y;
            }
            #pragma unroll
            for (int mf = 0; mf < 4; mf++)
                #pragma unroll
                for (int nf = 0; nf < 4; nf++)
                    mma8(acc[mf][nf], af[mf], bf[nf]);
        }
    }

    // epilogue
    #pragma unroll
    for (int mf = 0; mf < 4; mf++) {
        #pragma unroll
        for (int rr = 0; rr < 2; rr++) {
            const int m = bm + wm + mf*16 + g + rr*8;
            const int b = m >> 10;
            const int n = m & 1023;
            #pragma unroll
            for (int nf = 0; nf < 4; nf++) {
                const int c = bn + wn + nf*8 + 2*tig;
                float2 v2;
                v2.x = acc[mf][nf][rr*2 + 0];
                v2.y = acc[mf][nf][rr*2 + 1];
                if (MODE == 1) {
                    *(float2*)&Y[(size_t)m * Ncol + c] = v2;
                } else {
                    const int s = c / C_;
                    const int w = c - s * C_;
                    const int h = w >> 6;
                    const int d = w & 63;
                    const int idx = ((b*H_ + h)*N_ + n)*D_ + d;
                    if (s == 0)      *(float2*)&g_q[idx] = v2;
                    else if (s == 1) *(float2*)&g_k[idx] = v2;
                    else             *(float2*)&g_v[idx] = v2;
                }
            }
        }
    }
}

// ---------------------------------------------------------------------------
// Per-head LayerNorm over D=64. q rows also *SCALE (=1/8).
// ---------------------------------------------------------------------------
__global__ __launch_bounds__(256)
void ln_kernel()
{
    const int warp = (blockIdx.x * blockDim.x + threadIdx.x) >> 5;
    const int lane = threadIdx.x & 31;
    const int nrows = BH_ * N_;
    if (warp >= 2 * nrows) return;

    float* buf  = (warp < nrows) ? g_q : g_k;
    const float scale = (warp < nrows) ? 0.125f : 1.0f;
    const int row = (warp < nrows) ? warp : warp - nrows;

    float2 x = *(float2*)&buf[(size_t)row*64 + lane*2];
    float sum = x.x + x.y;
    #pragma unroll
    for (int o = 16; o > 0; o >>= 1) sum += __shfl_xor_sync(0xffffffffu, sum, o);
    const float mean = sum * (1.0f/64.0f);
    const float dx = x.x - mean, dy = x.y - mean;
    float vs = dx*dx + dy*dy;
    #pragma unroll
    for (int o = 16; o > 0; o >>= 1) vs += __shfl_xor_sync(0xffffffffu, vs, o);
    const float inv = rsqrtf(vs * (1.0f/64.0f) + 1e-5f) * scale;
    float2 out; out.x = dx * inv; out.y = dy * inv;
    *(float2*)&buf[(size_t)row*64 + lane*2] = out;
}

// ---------------------------------------------------------------------------
// Flash attention, tf32 mma. One block = 64 q rows of one (b,h), 128 threads.
// K and V^T tiles stored PRE-CONVERTED to tf32 bits (no cvt in mainloop).
// Q smem aliases P smem (Q consumed into registers before loop).
// ---------------------------------------------------------------------------
#define FPT 68

__global__ __launch_bounds__(128)
void flash_tf32()
{
    extern __shared__ char smemraw[];
    uint32_t* Ks = (uint32_t*)smemraw;        // [64][FPT] tf32 bits, K tile
    uint32_t* Vt = Ks + 64*FPT;               // [64][FPT] tf32 bits, V^T (row=d)
    float*    ps = (float*)(Vt + 64*FPT);     // [64][FPT] P (and Q at start)
    float*    qs = ps;

    const int bh    = blockIdx.y;
    const int qtile = blockIdx.x;
    const int b = bh / H_;
    const int h = bh - b * H_;

    const float* Q  = g_q + (size_t)bh * N_ * D_ + (size_t)qtile * 64 * D_;
    const float* Kp = g_k + (size_t)bh * N_ * D_;
    const float* Vp = g_v + (size_t)bh * N_ * D_;

    const int tid  = threadIdx.x;
    const int warp = tid >> 5, lane = tid & 31;
    const int g    = lane >> 2, tig = lane & 3;
    const int wband = warp * 16;

    // load q tile into qs (pitch FPT)
    for (int i = tid; i < 64*16; i += 128) {
        const int r = i >> 4, cv = (i & 15) << 2;
        *(float4*)&qs[r*FPT + cv] = *(const float4*)(Q + r*64 + cv);
    }
    __syncthreads();

    // hoist Q A-frags (tf32) — reused for all 16 KV tiles
    uint32_t qa[8][4];
    #pragma unroll
    for (int kf = 0; kf < 8; kf++) {
        const int r0 = wband + g;
        qa[kf][0] = f2tf(qs[ r0     *FPT + kf*8 + tig]);
        qa[kf][1] = f2tf(qs[(r0 + 8)*FPT + kf*8 + tig]);
        qa[kf][2] = f2tf(qs[ r0     *FPT + kf*8 + tig + 4]);
        qa[kf][3] = f2tf(qs[(r0 + 8)*FPT + kf*8 + tig + 4]);
    }

    float o[8][4];
    #pragma unroll
    for (int nf = 0; nf < 8; nf++)
        #pragma unroll
        for (int e = 0; e < 4; e++) o[nf][e] = 0.f;
    float m0 = -1e30f, m1 = -1e30f, l0 = 0.f, l1 = 0.f;

    for (int j = 0; j < 16; j++) {
        __syncthreads();  // prior iter done with Ks/Vt; j=0: Q hoisted by all
        for (int i = tid; i < 64*16; i += 128) {
            const int r = i >> 4, cv = (i & 15) << 2;
            float4 k4 = *(const float4*)(Kp + (size_t)j*4096 + r*64 + cv);
            Ks[r*FPT + cv + 0] = f2tf(k4.x);
            Ks[r*FPT + cv + 1] = f2tf(k4.y);
            Ks[r*FPT + cv + 2] = f2tf(k4.z);
            Ks[r*FPT + cv + 3] = f2tf(k4.w);
            float4 v4 = *(const float4*)(Vp + (size_t)j*4096 + r*64 + cv);
            Vt[(cv+0)*FPT + r] = f2tf(v4.x);
            Vt[(cv+1)*FPT + r] = f2tf(v4.y);
            Vt[(cv+2)*FPT + r] = f2tf(v4.z);
            Vt[(cv+3)*FPT + r] = f2tf(v4.w);
        }
        __syncthreads();

        // S = Q @ K^T   (warp: 16 rows x 64 cols)
        float s[8][4];
        #pragma unroll
        for (int nf = 0; nf < 8; nf++)
            #pragma unroll
            for (int e = 0; e < 4; e++) s[nf][e] = 0.f;

        #pragma unroll
        for (int kf = 0; kf < 8; kf++)
            #pragma unroll
            for (int nf = 0; nf < 8; nf++) {
                uint32_t bfr[2];
                bfr[0] = Ks[(nf*8 + g)*FPT + kf*8 + tig];
                bfr[1] = Ks[(nf*8 + g)*FPT + kf*8 + tig + 4];
                mma8(s[nf], qa[kf], bfr);
            }

        // online softmax (rows r0 = wband+g, r1 = r0+8)
        float mx0 = -1e30f, mx1 = -1e30f;
        #pragma unroll
        for (int nf = 0; nf < 8; nf++) {
            mx0 = fmaxf(mx0, fmaxf(s[nf][0], s[nf][1]));
            mx1 = fmaxf(mx1, fmaxf(s[nf][2], s[nf][3]));
        }
        mx0 = fmaxf(mx0, __shfl_xor_sync(0xffffffffu, mx0, 1));
        mx0 = fmaxf(mx0, __shfl_xor_sync(0xffffffffu, mx0, 2));
        mx1 = fmaxf(mx1, __shfl_xor_sync(0xffffffffu, mx1, 1));
        mx1 = fmaxf(mx1, __shfl_xor_sync(0xffffffffu, mx1, 2));

        const float mn0 = fmaxf(m0, mx0);
        const float mn1 = fmaxf(m1, mx1);
        const float corr0 = __expf(m0 - mn0);
        const float corr1 = __expf(m1 - mn1);
        m0 = mn0; m1 = mn1;

        float rs0 = 0.f, rs1 = 0.f;
        #pragma unroll
        for (int nf = 0; nf < 8; nf++) {
            const float p0 = __expf(s[nf][0] - mn0);
            const float p1 = __expf(s[nf][1] - mn0);
            const float p2 = __expf(s[nf][2] - mn1);
            const float p3 = __expf(s[nf][3] - mn1);
            rs0 += p0 + p1;
            rs1 += p2 + p3;
            float2 w0; w0.x = p0; w0.y = p1;
            float2 w1; w1.x = p2; w1.y = p3;
            *(float2*)&ps[(wband + g    )*FPT + nf*8 + 2*tig] = w0;
            *(float2*)&ps[(wband + g + 8)*FPT + nf*8 + 2*tig] = w1;
        }
        rs0 += __shfl_xor_sync(0xffffffffu, rs0, 1);
        rs0 += __shfl_xor_sync(0xffffffffu, rs0, 2);
        rs1 += __shfl_xor_sync(0xffffffffu, rs1, 1);
        rs1 += __shfl_xor_sync(0xffffffffu, rs1, 2);
        l0 = l0 * corr0 + rs0;
        l1 = l1 * corr1 + rs1;

        #pragma unroll
        for (int nf = 0; nf < 8; nf++) {
            o[nf][0] *= corr0; o[nf][1] *= corr0;
            o[nf][2] *= corr1; o[nf][3] *= corr1;
        }
        __syncwarp();

        // O += P @ V
        #pragma unroll
        for (int kf = 0; kf < 8; kf++) {
            uint32_t pa[4];
            pa[0] = f2tf(ps[(wband + g    )*FPT + kf*8 + tig]);
            pa[1] = f2tf(ps[(wband + g + 8)*FPT + kf*8 + tig]);
            pa[2] = f2tf(ps[(wband + g    )*FPT + kf*8 + tig + 4]);
            pa[3] = f2tf(ps[(wband + g + 8)*FPT + kf*8 + tig + 4]);
            #pragma unroll
            for (int nf = 0; nf < 8; nf++) {
                uint32_t bv[2];
                bv[0] = Vt[(nf*8 + g)*FPT + kf*8 + tig];
                bv[1] = Vt[(nf*8 + g)*FPT + kf*8 + tig + 4];
                mma8(o[nf], pa, bv);
            }
        }
        __syncwarp();  // ps reads done before next iter overwrites
    }

    // epilogue: O / l  -> g_ao [B,N,C], c = h*64 + d
    const float inv0 = 1.0f / l0;
    const float inv1 = 1.0f / l1;
    const int n0 = qtile*64 + wband + g;
    const int n1 = n0 + 8;
    #pragma unroll
    for (int nf = 0; nf < 8; nf++) {
        const int d = h*64 + nf*8 + 2*tig;
        float2 w0; w0.x = o[nf][0]*inv0; w0.y = o[nf][1]*inv0;
        float2 w1; w1.x = o[nf][2]*inv1; w1.y = o[nf][3]*inv1;
        *(float2*)&g_ao[((size_t)b*N_ + n0)*C_ + d] = w0;
        *(float2*)&g_ao[((size_t)b*N_ + n1)*C_ + d] = w1;
    }
}

// ---------------------------------------------------------------------------
extern "C" void kernel_launch(void* const* d_in, const int* in_sizes, int n_in,
                              void* d_out, int out_size)
{
    const float* x     = (const float*)d_in[0];   // [B,N,C]
    const float* wqkv  = (const float*)d_in[1];   // [3C,C]
    const float* wproj = (const float*)d_in[2];   // [C,C]
    float* out = (float*)d_out;                   // [B,N,C]

    // 1) QKV GEMM -> q/k/v [B,H,N,D]
    {
        dim3 grid(3*C_/128, (B_*N_)/128);   // (18, 64)
        gemm_tf32<0><<<grid, 256>>>(x, wqkv, nullptr, B_*N_, 3*C_, C_);
    }

    // 2) LayerNorm on q (*SCALE) and k
    {
        const int warps = 2 * BH_ * N_;
        const int blocks = (warps * 32 + 255) / 256;
        ln_kernel<<<blocks, 256>>>();
    }

    // 3) Flash attention -> g_ao
    {
        const int smem_bytes = (2*64*FPT)*(int)sizeof(uint32_t)
                             + (64*FPT)*(int)sizeof(float);   // 52224
        cudaFuncSetAttribute(flash_tf32,
                             cudaFuncAttributeMaxDynamicSharedMemorySize, smem_bytes);
        dim3 grid(N_/64, BH_);   // (16, 96)
        flash_tf32<<<grid, 128, smem_bytes>>>();
    }

    // 4) Output projection
    {
        dim3 grid(C_/128, (B_*N_)/128);     // (6, 64)
        gemm_tf32<1><<<grid, 256>>>(nullptr, wproj, out, B_*N_, C_, C_);
    }
}

// round 5
// speedup vs baseline: 1.6166x; 1.1004x over previous
#include <cuda_runtime.h>
#include <math.h>
#include <stdint.h>

#define B_ 8
#define N_ 1024
#define C_ 768
#define H_ 12
#define D_ 64
#define BH_ (B_*H_)

// Scratch (device globals — no allocation allowed)
__device__ float g_q [BH_*N_*D_];   // [B,H,N,D]
__device__ float g_k [BH_*N_*D_];
__device__ float g_v [BH_*N_*D_];
__device__ float g_ao[B_*N_*C_];    // attention output in [B,N,C]

// ---------------------------------------------------------------------------
// tf32 helpers
// ---------------------------------------------------------------------------
__device__ __forceinline__ uint32_t f2tf(float f) {
    uint32_t u;
    asm("cvt.rna.tf32.f32 %0, %1;" : "=r"(u) : "f"(f));
    return u;
}

__device__ __forceinline__ void mma8(float* c, const uint32_t* a, const uint32_t* b) {
    asm volatile(
        "mma.sync.aligned.m16n8k8.row.col.f32.tf32.tf32.f32 "
        "{%0,%1,%2,%3},{%4,%5,%6,%7},{%8,%9},{%0,%1,%2,%3};"
        : "+f"(c[0]), "+f"(c[1]), "+f"(c[2]), "+f"(c[3])
        : "r"(a[0]), "r"(a[1]), "r"(a[2]), "r"(a[3]), "r"(b[0]), "r"(b[1]));
}

// Paired-column swizzled smem addressing: 8 uint2 slots per 16-float row.
// Slot s = kk*4+pos holds tf32 bits of cols (kk*8+pos, kk*8+pos+4).
__device__ __forceinline__ int sw16(int r, int s) {
    return r*8 + (s ^ (((r&2)<<1) ^ ((r>>2)&3)));
}

// ---------------------------------------------------------------------------
// tf32 GEMM: Y[m,c] = sum_k A[m,k] * W[c,k]
// Block 128x128, BK=16, 256 threads = 8 warps (2x4), warp tile 64x32.
// Double-buffered smem of pre-converted tf32 bits (1 sync per k-slice).
// MODE 0: scatter into g_q/g_k/g_v;  MODE 1: A := g_ao, row-major store.
// ---------------------------------------------------------------------------
template<int MODE>
__global__ __launch_bounds__(256, 2)
void gemm_tf32(const float* __restrict__ A, const float* __restrict__ W,
               float* __restrict__ Y, int M, int Ncol, int K)
{
    __shared__ uint2 As2[2][128*8];
    __shared__ uint2 Ws2[2][128*8];

    const int tid  = threadIdx.x;
    const int warp = tid >> 5, lane = tid & 31;
    const int g    = lane >> 2, tig = lane & 3;
    const int wm   = (warp >> 2) * 64;
    const int wn   = (warp & 3)  * 32;
    const int bm   = blockIdx.y * 128;
    const int bn   = blockIdx.x * 128;

    if (MODE == 1) A = g_ao;

    const int lrow  = tid & 127;
    const int lhalf = tid >> 7;          // 0: cols 0-7, 1: cols 8-15

    const float* Ap = A + (size_t)(bm + lrow) * K + lhalf*8;
    const float* Wp = W + (size_t)(bn + lrow) * K + lhalf*8;

    float acc[4][4][4];
    #pragma unroll
    for (int i = 0; i < 4; i++)
        #pragma unroll
        for (int j = 0; j < 4; j++)
            #pragma unroll
            for (int e = 0; e < 4; e++) acc[i][j][e] = 0.f;

    float va[8], vw[8];
    // load slice 0
    *(float4*)&va[0] = *(const float4*)Ap;
    *(float4*)&va[4] = *(const float4*)(Ap + 4);
    *(float4*)&vw[0] = *(const float4*)Wp;
    *(float4*)&vw[4] = *(const float4*)(Wp + 4);
    // store slice 0 into buffer 0
    #pragma unroll
    for (int pos = 0; pos < 4; pos++) {
        As2[0][sw16(lrow, lhalf*4 + pos)] = make_uint2(f2tf(va[pos]), f2tf(va[pos+4]));
        Ws2[0][sw16(lrow, lhalf*4 + pos)] = make_uint2(f2tf(vw[pos]), f2tf(vw[pos+4]));
    }
    // prefetch slice 1
    if (16 < K) {
        Ap += 16; Wp += 16;
        *(float4*)&va[0] = *(const float4*)Ap;
        *(float4*)&va[4] = *(const float4*)(Ap + 4);
        *(float4*)&vw[0] = *(const float4*)Wp;
        *(float4*)&vw[4] = *(const float4*)(Wp + 4);
    }
    __syncthreads();

    const int nk = K >> 4;
    for (int i = 0; i < nk; i++) {
        const int cur = i & 1;
        // store slice i+1 into the other buffer (regs were prefetched)
        if (i + 1 < nk) {
            #pragma unroll
            for (int pos = 0; pos < 4; pos++) {
                As2[cur^1][sw16(lrow, lhalf*4 + pos)] =
                    make_uint2(f2tf(va[pos]), f2tf(va[pos+4]));
                Ws2[cur^1][sw16(lrow, lhalf*4 + pos)] =
                    make_uint2(f2tf(vw[pos]), f2tf(vw[pos+4]));
            }
        }
        // prefetch slice i+2
        if (i + 2 < nk) {
            Ap += 16; Wp += 16;
            *(float4*)&va[0] = *(const float4*)Ap;
            *(float4*)&va[4] = *(const float4*)(Ap + 4);
            *(float4*)&vw[0] = *(const float4*)Wp;
            *(float4*)&vw[4] = *(const float4*)(Wp + 4);
        }

        // compute on buffer cur
        #pragma unroll
        for (int kk = 0; kk < 2; kk++) {
            uint32_t af[4][4];
            #pragma unroll
            for (int mf = 0; mf < 4; mf++) {
                const int rA = wm + mf*16 + g;
                uint2 lo = As2[cur][sw16(rA,     kk*4 + tig)];
                uint2 hi = As2[cur][sw16(rA + 8, kk*4 + tig)];
                af[mf][0] = lo.x; af[mf][1] = hi.x;
                af[mf][2] = lo.y; af[mf][3] = hi.y;
            }
            uint32_t bf[4][2];
            #pragma unroll
            for (int nf = 0; nf < 4; nf++) {
                uint2 bb = Ws2[cur][sw16(wn + nf*8 + g, kk*4 + tig)];
                bf[nf][0] = bb.x; bf[nf][1] = bb.y;
            }
            #pragma unroll
            for (int mf = 0; mf < 4; mf++)
                #pragma unroll
                for (int nf = 0; nf < 4; nf++)
                    mma8(acc[mf][nf], af[mf], bf[nf]);
        }
        __syncthreads();
    }

    // epilogue
    #pragma unroll
    for (int mf = 0; mf < 4; mf++) {
        #pragma unroll
        for (int rr = 0; rr < 2; rr++) {
            const int m = bm + wm + mf*16 + g + rr*8;
            const int b = m >> 10;
            const int n = m & 1023;
            #pragma unroll
            for (int nf = 0; nf < 4; nf++) {
                const int c = bn + wn + nf*8 + 2*tig;
                float2 v2;
                v2.x = acc[mf][nf][rr*2 + 0];
                v2.y = acc[mf][nf][rr*2 + 1];
                if (MODE == 1) {
                    *(float2*)&Y[(size_t)m * Ncol + c] = v2;
                } else {
                    const int s = c / C_;
                    const int w = c - s * C_;
                    const int h = w >> 6;
                    const int d = w & 63;
                    const int idx = ((b*H_ + h)*N_ + n)*D_ + d;
                    if (s == 0)      *(float2*)&g_q[idx] = v2;
                    else if (s == 1) *(float2*)&g_k[idx] = v2;
                    else             *(float2*)&g_v[idx] = v2;
                }
            }
        }
    }
}

// ---------------------------------------------------------------------------
// Per-head LayerNorm over D=64. q rows also *SCALE (=1/8).
// ---------------------------------------------------------------------------
__global__ __launch_bounds__(256)
void ln_kernel()
{
    const int warp = (blockIdx.x * blockDim.x + threadIdx.x) >> 5;
    const int lane = threadIdx.x & 31;
    const int nrows = BH_ * N_;
    if (warp >= 2 * nrows) return;

    float* buf  = (warp < nrows) ? g_q : g_k;
    const float scale = (warp < nrows) ? 0.125f : 1.0f;
    const int row = (warp < nrows) ? warp : warp - nrows;

    float2 x = *(float2*)&buf[(size_t)row*64 + lane*2];
    float sum = x.x + x.y;
    #pragma unroll
    for (int o = 16; o > 0; o >>= 1) sum += __shfl_xor_sync(0xffffffffu, sum, o);
    const float mean = sum * (1.0f/64.0f);
    const float dx = x.x - mean, dy = x.y - mean;
    float vs = dx*dx + dy*dy;
    #pragma unroll
    for (int o = 16; o > 0; o >>= 1) vs += __shfl_xor_sync(0xffffffffu, vs, o);
    const float inv = rsqrtf(vs * (1.0f/64.0f) + 1e-5f) * scale;
    float2 out; out.x = dx * inv; out.y = dy * inv;
    *(float2*)&buf[(size_t)row*64 + lane*2] = out;
}

// ---------------------------------------------------------------------------
// Flash attention, tf32 mma. One block = 64 q rows of one (b,h), 128 threads.
// K and V^T tiles stored PRE-CONVERTED to tf32 bits (no cvt in mainloop).
// Q smem aliases P smem (Q consumed into registers before loop).
// ---------------------------------------------------------------------------
#define FPT 68

__global__ __launch_bounds__(128, 3)
void flash_tf32()
{
    extern __shared__ char smemraw[];
    uint32_t* Ks = (uint32_t*)smemraw;        // [64][FPT] tf32 bits, K tile
    uint32_t* Vt = Ks + 64*FPT;               // [64][FPT] tf32 bits, V^T (row=d)
    float*    ps = (float*)(Vt + 64*FPT);     // [64][FPT] P (and Q at start)
    float*    qs = ps;

    const int bh    = blockIdx.y;
    const int qtile = blockIdx.x;
    const int b = bh / H_;
    const int h = bh - b * H_;

    const float* Q  = g_q + (size_t)bh * N_ * D_ + (size_t)qtile * 64 * D_;
    const float* Kp = g_k + (size_t)bh * N_ * D_;
    const float* Vp = g_v + (size_t)bh * N_ * D_;

    const int tid  = threadIdx.x;
    const int warp = tid >> 5, lane = tid & 31;
    const int g    = lane >> 2, tig = lane & 3;
    const int wband = warp * 16;

    // load q tile into qs (pitch FPT)
    for (int i = tid; i < 64*16; i += 128) {
        const int r = i >> 4, cv = (i & 15) << 2;
        *(float4*)&qs[r*FPT + cv] = *(const float4*)(Q + r*64 + cv);
    }
    __syncthreads();

    // hoist Q A-frags (tf32) — reused for all 16 KV tiles
    uint32_t qa[8][4];
    #pragma unroll
    for (int kf = 0; kf < 8; kf++) {
        const int r0 = wband + g;
        qa[kf][0] = f2tf(qs[ r0     *FPT + kf*8 + tig]);
        qa[kf][1] = f2tf(qs[(r0 + 8)*FPT + kf*8 + tig]);
        qa[kf][2] = f2tf(qs[ r0     *FPT + kf*8 + tig + 4]);
        qa[kf][3] = f2tf(qs[(r0 + 8)*FPT + kf*8 + tig + 4]);
    }

    float o[8][4];
    #pragma unroll
    for (int nf = 0; nf < 8; nf++)
        #pragma unroll
        for (int e = 0; e < 4; e++) o[nf][e] = 0.f;
    float m0 = -1e30f, m1 = -1e30f, l0 = 0.f, l1 = 0.f;

    for (int j = 0; j < 16; j++) {
        __syncthreads();  // prior iter done with Ks/Vt; j=0: Q hoisted by all
        for (int i = tid; i < 64*16; i += 128) {
            const int r = i >> 4, cv = (i & 15) << 2;
            float4 k4 = *(const float4*)(Kp + (size_t)j*4096 + r*64 + cv);
            Ks[r*FPT + cv + 0] = f2tf(k4.x);
            Ks[r*FPT + cv + 1] = f2tf(k4.y);
            Ks[r*FPT + cv + 2] = f2tf(k4.z);
            Ks[r*FPT + cv + 3] = f2tf(k4.w);
            float4 v4 = *(const float4*)(Vp + (size_t)j*4096 + r*64 + cv);
            Vt[(cv+0)*FPT + r] = f2tf(v4.x);
            Vt[(cv+1)*FPT + r] = f2tf(v4.y);
            Vt[(cv+2)*FPT + r] = f2tf(v4.z);
            Vt[(cv+3)*FPT + r] = f2tf(v4.w);
        }
        __syncthreads();

        // S = Q @ K^T   (warp: 16 rows x 64 cols)
        float s[8][4];
        #pragma unroll
        for (int nf = 0; nf < 8; nf++)
            #pragma unroll
            for (int e = 0; e < 4; e++) s[nf][e] = 0.f;

        #pragma unroll
        for (int kf = 0; kf < 8; kf++)
            #pragma unroll
            for (int nf = 0; nf < 8; nf++) {
                uint32_t bfr[2];
                bfr[0] = Ks[(nf*8 + g)*FPT + kf*8 + tig];
                bfr[1] = Ks[(nf*8 + g)*FPT + kf*8 + tig + 4];
                mma8(s[nf], qa[kf], bfr);
            }

        // online softmax (rows r0 = wband+g, r1 = r0+8)
        float mx0 = -1e30f, mx1 = -1e30f;
        #pragma unroll
        for (int nf = 0; nf < 8; nf++) {
            mx0 = fmaxf(mx0, fmaxf(s[nf][0], s[nf][1]));
            mx1 = fmaxf(mx1, fmaxf(s[nf][2], s[nf][3]));
        }
        mx0 = fmaxf(mx0, __shfl_xor_sync(0xffffffffu, mx0, 1));
        mx0 = fmaxf(mx0, __shfl_xor_sync(0xffffffffu, mx0, 2));
        mx1 = fmaxf(mx1, __shfl_xor_sync(0xffffffffu, mx1, 1));
        mx1 = fmaxf(mx1, __shfl_xor_sync(0xffffffffu, mx1, 2));

        const float mn0 = fmaxf(m0, mx0);
        const float mn1 = fmaxf(m1, mx1);
        const float corr0 = __expf(m0 - mn0);
        const float corr1 = __expf(m1 - mn1);
        m0 = mn0; m1 = mn1;

        float rs0 = 0.f, rs1 = 0.f;
        #pragma unroll
        for (int nf = 0; nf < 8; nf++) {
            const float p0 = __expf(s[nf][0] - mn0);
            const float p1 = __expf(s[nf][1] - mn0);
            const float p2 = __expf(s[nf][2] - mn1);
            const float p3 = __expf(s[nf][3] - mn1);
            rs0 += p0 + p1;
            rs1 += p2 + p3;
            float2 w0; w0.x = p0; w0.y = p1;
            float2 w1; w1.x = p2; w1.y = p3;
            *(float2*)&ps[(wband + g    )*FPT + nf*8 + 2*tig] = w0;
            *(float2*)&ps[(wband + g + 8)*FPT + nf*8 + 2*tig] = w1;
        }
        rs0 += __shfl_xor_sync(0xffffffffu, rs0, 1);
        rs0 += __shfl_xor_sync(0xffffffffu, rs0, 2);
        rs1 += __shfl_xor_sync(0xffffffffu, rs1, 1);
        rs1 += __shfl_xor_sync(0xffffffffu, rs1, 2);
        l0 = l0 * corr0 + rs0;
        l1 = l1 * corr1 + rs1;

        #pragma unroll
        for (int nf = 0; nf < 8; nf++) {
            o[nf][0] *= corr0; o[nf][1] *= corr0;
            o[nf][2] *= corr1; o[nf][3] *= corr1;
        }
        __syncwarp();

        // O += P @ V
        #pragma unroll
        for (int kf = 0; kf < 8; kf++) {
            uint32_t pa[4];
            pa[0] = f2tf(ps[(wband + g    )*FPT + kf*8 + tig]);
            pa[1] = f2tf(ps[(wband + g + 8)*FPT + kf*8 + tig]);
            pa[2] = f2tf(ps[(wband + g    )*FPT + kf*8 + tig + 4]);
            pa[3] = f2tf(ps[(wband + g + 8)*FPT + kf*8 + tig + 4]);
            #pragma unroll
            for (int nf = 0; nf < 8; nf++) {
                uint32_t bv[2];
                bv[0] = Vt[(nf*8 + g)*FPT + kf*8 + tig];
                bv[1] = Vt[(nf*8 + g)*FPT + kf*8 + tig + 4];
                mma8(o[nf], pa, bv);
            }
        }
        __syncwarp();  // ps reads done before next iter overwrites
    }

    // epilogue: O / l  -> g_ao [B,N,C], c = h*64 + d
    const float inv0 = 1.0f / l0;
    const float inv1 = 1.0f / l1;
    const int n0 = qtile*64 + wband + g;
    const int n1 = n0 + 8;
    #pragma unroll
    for (int nf = 0; nf < 8; nf++) {
        const int d = h*64 + nf*8 + 2*tig;
        float2 w0; w0.x = o[nf][0]*inv0; w0.y = o[nf][1]*inv0;
        float2 w1; w1.x = o[nf][2]*inv1; w1.y = o[nf][3]*inv1;
        *(float2*)&g_ao[((size_t)b*N_ + n0)*C_ + d] = w0;
        *(float2*)&g_ao[((size_t)b*N_ + n1)*C_ + d] = w1;
    }
}

// ---------------------------------------------------------------------------
extern "C" void kernel_launch(void* const* d_in, const int* in_sizes, int n_in,
                              void* d_out, int out_size)
{
    const float* x     = (const float*)d_in[0];   // [B,N,C]
    const float* wqkv  = (const float*)d_in[1];   // [3C,C]
    const float* wproj = (const float*)d_in[2];   // [C,C]
    float* out = (float*)d_out;                   // [B,N,C]

    // 1) QKV GEMM -> q/k/v [B,H,N,D]
    {
        dim3 grid(3*C_/128, (B_*N_)/128);   // (18, 64)
        gemm_tf32<0><<<grid, 256>>>(x, wqkv, nullptr, B_*N_, 3*C_, C_);
    }

    // 2) LayerNorm on q (*SCALE) and k
    {
        const int warps = 2 * BH_ * N_;
        const int blocks = (warps * 32 + 255) / 256;
        ln_kernel<<<blocks, 256>>>();
    }

    // 3) Flash attention -> g_ao
    {
        const int smem_bytes = (2*64*FPT)*(int)sizeof(uint32_t)
                             + (64*FPT)*(int)sizeof(float);   // 52224
        cudaFuncSetAttribute(flash_tf32,
                             cudaFuncAttributeMaxDynamicSharedMemorySize, smem_bytes);
        dim3 grid(N_/64, BH_);   // (16, 96)
        flash_tf32<<<grid, 128, smem_bytes>>>();
    }

    // 4) Output projection
    {
        dim3 grid(C_/128, (B_*N_)/128);     // (6, 64)
        gemm_tf32<1><<<grid, 256>>>(nullptr, wproj, out, B_*N_, C_, C_);
    }
}

// round 6
// speedup vs baseline: 1.7597x; 1.0885x over previous
#include <cuda_runtime.h>
#include <math.h>
#include <stdint.h>

#define B_ 8
#define N_ 1024
#define C_ 768
#define H_ 12
#define D_ 64
#define BH_ (B_*H_)

// Scratch (device globals — no allocation allowed)
__device__ float g_q [BH_*N_*D_];   // [B,H,N,D]
__device__ float g_k [BH_*N_*D_];
__device__ float g_v [BH_*N_*D_];
__device__ float g_ao[B_*N_*C_];    // attention output in [B,N,C]

// ---------------------------------------------------------------------------
// tf32 helpers
// ---------------------------------------------------------------------------
__device__ __forceinline__ uint32_t f2tf(float f) {
    uint32_t u;
    asm("cvt.rna.tf32.f32 %0, %1;" : "=r"(u) : "f"(f));
    return u;
}

__device__ __forceinline__ void mma8(float* c, const uint32_t* a, const uint32_t* b) {
    asm volatile(
        "mma.sync.aligned.m16n8k8.row.col.f32.tf32.tf32.f32 "
        "{%0,%1,%2,%3},{%4,%5,%6,%7},{%8,%9},{%0,%1,%2,%3};"
        : "+f"(c[0]), "+f"(c[1]), "+f"(c[2]), "+f"(c[3])
        : "r"(a[0]), "r"(a[1]), "r"(a[2]), "r"(a[3]), "r"(b[0]), "r"(b[1]));
}

// ---------------------------------------------------------------------------
// tf32 GEMM: Y[m,c] = sum_k A[m,k] * W[c,k]
// R2 structure: BM=BN=128, BK=16, 256 threads = 8 warps (2x4), warp 64x32,
// KP=20 pitch (fragment loads verified conflict-free).
// ONE change vs R2: smem holds PRE-CONVERTED tf32 bits (no cvt in mainloop).
// MODE 0: scatter into g_q/g_k/g_v;  MODE 1: A := g_ao, row-major store.
// ---------------------------------------------------------------------------
#define KP 20

template<int MODE>
__global__ __launch_bounds__(256)
void gemm_tf32(const float* __restrict__ A, const float* __restrict__ W,
               float* __restrict__ Y, int M, int Ncol, int K)
{
    __shared__ uint32_t As[128*KP];
    __shared__ uint32_t Ws[128*KP];

    const int tid  = threadIdx.x;
    const int warp = tid >> 5, lane = tid & 31;
    const int g    = lane >> 2, tig = lane & 3;
    const int wm   = (warp >> 2) * 64;
    const int wn   = (warp & 3)  * 32;
    const int bm   = blockIdx.y * 128;
    const int bn   = blockIdx.x * 128;

    if (MODE == 1) A = g_ao;

    const int lr = tid >> 1;        // 0..127
    const int lc = (tid & 1) * 8;   // 0 or 8

    const float* Ap = A + (size_t)(bm + lr) * K + lc;
    const float* Wp = W + (size_t)(bn + lr) * K + lc;

    float acc[4][4][4];
    #pragma unroll
    for (int i = 0; i < 4; i++)
        #pragma unroll
        for (int j = 0; j < 4; j++)
            #pragma unroll
            for (int e = 0; e < 4; e++) acc[i][j][e] = 0.f;

    float4 ra0 = *(const float4*)Ap;
    float4 ra1 = *(const float4*)(Ap + 4);
    float4 rw0 = *(const float4*)Wp;
    float4 rw1 = *(const float4*)(Wp + 4);

    for (int k0 = 0; k0 < K; k0 += 16) {
        __syncthreads();
        {
            uint4 ua0 = make_uint4(f2tf(ra0.x), f2tf(ra0.y), f2tf(ra0.z), f2tf(ra0.w));
            uint4 ua1 = make_uint4(f2tf(ra1.x), f2tf(ra1.y), f2tf(ra1.z), f2tf(ra1.w));
            uint4 uw0 = make_uint4(f2tf(rw0.x), f2tf(rw0.y), f2tf(rw0.z), f2tf(rw0.w));
            uint4 uw1 = make_uint4(f2tf(rw1.x), f2tf(rw1.y), f2tf(rw1.z), f2tf(rw1.w));
            *(uint4*)&As[lr*KP + lc]     = ua0;
            *(uint4*)&As[lr*KP + lc + 4] = ua1;
            *(uint4*)&Ws[lr*KP + lc]     = uw0;
            *(uint4*)&Ws[lr*KP + lc + 4] = uw1;
        }
        __syncthreads();

        if (k0 + 16 < K) {
            Ap += 16; Wp += 16;
            ra0 = *(const float4*)Ap;
            ra1 = *(const float4*)(Ap + 4);
            rw0 = *(const float4*)Wp;
            rw1 = *(const float4*)(Wp + 4);
        }

        #pragma unroll
        for (int kk = 0; kk < 16; kk += 8) {
            uint32_t af[4][4];
            #pragma unroll
            for (int mf = 0; mf < 4; mf++) {
                const int r0 = wm + mf*16 + g;
                af[mf][0] = As[ r0     *KP + kk + tig];
                af[mf][1] = As[(r0 + 8)*KP + kk + tig];
                af[mf][2] = As[ r0     *KP + kk + tig + 4];
                af[mf][3] = As[(r0 + 8)*KP + kk + tig + 4];
            }
            uint32_t bf[4][2];
            #pragma unroll
            for (int nf = 0; nf < 4; nf++) {
                const int nr = wn + nf*8 + g;
                bf[nf][0] = Ws[nr*KP + kk + tig];
                bf[nf][1] = Ws[nr*KP + kk + tig + 4];
            }
            #pragma unroll
            for (int mf = 0; mf < 4; mf++)
                #pragma unroll
                for (int nf = 0; nf < 4; nf++)
                    mma8(acc[mf][nf], af[mf], bf[nf]);
        }
    }

    // epilogue
    #pragma unroll
    for (int mf = 0; mf < 4; mf++) {
        #pragma unroll
        for (int rr = 0; rr < 2; rr++) {
            const int m = bm + wm + mf*16 + g + rr*8;
            const int b = m >> 10;
            const int n = m & 1023;
            #pragma unroll
            for (int nf = 0; nf < 4; nf++) {
                const int c = bn + wn + nf*8 + 2*tig;
                float2 v2;
                v2.x = acc[mf][nf][rr*2 + 0];
                v2.y = acc[mf][nf][rr*2 + 1];
                if (MODE == 1) {
                    *(float2*)&Y[(size_t)m * Ncol + c] = v2;
                } else {
                    const int s = c / C_;
                    const int w = c - s * C_;
                    const int h = w >> 6;
                    const int d = w & 63;
                    const int idx = ((b*H_ + h)*N_ + n)*D_ + d;
                    if (s == 0)      *(float2*)&g_q[idx] = v2;
                    else if (s == 1) *(float2*)&g_k[idx] = v2;
                    else             *(float2*)&g_v[idx] = v2;
                }
            }
        }
    }
}

// ---------------------------------------------------------------------------
// Per-head LayerNorm over D=64. q rows also *SCALE (=1/8).
// ---------------------------------------------------------------------------
__global__ __launch_bounds__(256)
void ln_kernel()
{
    const int warp = (blockIdx.x * blockDim.x + threadIdx.x) >> 5;
    const int lane = threadIdx.x & 31;
    const int nrows = BH_ * N_;
    if (warp >= 2 * nrows) return;

    float* buf  = (warp < nrows) ? g_q : g_k;
    const float scale = (warp < nrows) ? 0.125f : 1.0f;
    const int row = (warp < nrows) ? warp : warp - nrows;

    float2 x = *(float2*)&buf[(size_t)row*64 + lane*2];
    float sum = x.x + x.y;
    #pragma unroll
    for (int o = 16; o > 0; o >>= 1) sum += __shfl_xor_sync(0xffffffffu, sum, o);
    const float mean = sum * (1.0f/64.0f);
    const float dx = x.x - mean, dy = x.y - mean;
    float vs = dx*dx + dy*dy;
    #pragma unroll
    for (int o = 16; o > 0; o >>= 1) vs += __shfl_xor_sync(0xffffffffu, vs, o);
    const float inv = rsqrtf(vs * (1.0f/64.0f) + 1e-5f) * scale;
    float2 out; out.x = dx * inv; out.y = dy * inv;
    *(float2*)&buf[(size_t)row*64 + lane*2] = out;
}

// ---------------------------------------------------------------------------
// Flash attention, tf32 mma (R5 version — measured ~209us).
// One block = 64 q rows of one (b,h), 128 threads.
// K and V^T tiles stored PRE-CONVERTED to tf32 bits.
// Q smem aliases P smem (Q consumed into registers before loop).
// ---------------------------------------------------------------------------
#define FPT 68

__global__ __launch_bounds__(128, 3)
void flash_tf32()
{
    extern __shared__ char smemraw[];
    uint32_t* Ks = (uint32_t*)smemraw;        // [64][FPT] tf32 bits, K tile
    uint32_t* Vt = Ks + 64*FPT;               // [64][FPT] tf32 bits, V^T (row=d)
    float*    ps = (float*)(Vt + 64*FPT);     // [64][FPT] P (and Q at start)
    float*    qs = ps;

    const int bh    = blockIdx.y;
    const int qtile = blockIdx.x;
    const int b = bh / H_;
    const int h = bh - b * H_;

    const float* Q  = g_q + (size_t)bh * N_ * D_ + (size_t)qtile * 64 * D_;
    const float* Kp = g_k + (size_t)bh * N_ * D_;
    const float* Vp = g_v + (size_t)bh * N_ * D_;

    const int tid  = threadIdx.x;
    const int warp = tid >> 5, lane = tid & 31;
    const int g    = lane >> 2, tig = lane & 3;
    const int wband = warp * 16;

    // load q tile into qs (pitch FPT)
    for (int i = tid; i < 64*16; i += 128) {
        const int r = i >> 4, cv = (i & 15) << 2;
        *(float4*)&qs[r*FPT + cv] = *(const float4*)(Q + r*64 + cv);
    }
    __syncthreads();

    // hoist Q A-frags (tf32) — reused for all 16 KV tiles
    uint32_t qa[8][4];
    #pragma unroll
    for (int kf = 0; kf < 8; kf++) {
        const int r0 = wband + g;
        qa[kf][0] = f2tf(qs[ r0     *FPT + kf*8 + tig]);
        qa[kf][1] = f2tf(qs[(r0 + 8)*FPT + kf*8 + tig]);
        qa[kf][2] = f2tf(qs[ r0     *FPT + kf*8 + tig + 4]);
        qa[kf][3] = f2tf(qs[(r0 + 8)*FPT + kf*8 + tig + 4]);
    }

    float o[8][4];
    #pragma unroll
    for (int nf = 0; nf < 8; nf++)
        #pragma unroll
        for (int e = 0; e < 4; e++) o[nf][e] = 0.f;
    float m0 = -1e30f, m1 = -1e30f, l0 = 0.f, l1 = 0.f;

    for (int j = 0; j < 16; j++) {
        __syncthreads();  // prior iter done with Ks/Vt; j=0: Q hoisted by all
        for (int i = tid; i < 64*16; i += 128) {
            const int r = i >> 4, cv = (i & 15) << 2;
            float4 k4 = *(const float4*)(Kp + (size_t)j*4096 + r*64 + cv);
            Ks[r*FPT + cv + 0] = f2tf(k4.x);
            Ks[r*FPT + cv + 1] = f2tf(k4.y);
            Ks[r*FPT + cv + 2] = f2tf(k4.z);
            Ks[r*FPT + cv + 3] = f2tf(k4.w);
            float4 v4 = *(const float4*)(Vp + (size_t)j*4096 + r*64 + cv);
            Vt[(cv+0)*FPT + r] = f2tf(v4.x);
            Vt[(cv+1)*FPT + r] = f2tf(v4.y);
            Vt[(cv+2)*FPT + r] = f2tf(v4.z);
            Vt[(cv+3)*FPT + r] = f2tf(v4.w);
        }
        __syncthreads();

        // S = Q @ K^T   (warp: 16 rows x 64 cols)
        float s[8][4];
        #pragma unroll
        for (int nf = 0; nf < 8; nf++)
            #pragma unroll
            for (int e = 0; e < 4; e++) s[nf][e] = 0.f;

        #pragma unroll
        for (int kf = 0; kf < 8; kf++)
            #pragma unroll
            for (int nf = 0; nf < 8; nf++) {
                uint32_t bfr[2];
                bfr[0] = Ks[(nf*8 + g)*FPT + kf*8 + tig];
                bfr[1] = Ks[(nf*8 + g)*FPT + kf*8 + tig + 4];
                mma8(s[nf], qa[kf], bfr);
            }

        // online softmax (rows r0 = wband+g, r1 = r0+8)
        float mx0 = -1e30f, mx1 = -1e30f;
        #pragma unroll
        for (int nf = 0; nf < 8; nf++) {
            mx0 = fmaxf(mx0, fmaxf(s[nf][0], s[nf][1]));
            mx1 = fmaxf(mx1, fmaxf(s[nf][2], s[nf][3]));
        }
        mx0 = fmaxf(mx0, __shfl_xor_sync(0xffffffffu, mx0, 1));
        mx0 = fmaxf(mx0, __shfl_xor_sync(0xffffffffu, mx0, 2));
        mx1 = fmaxf(mx1, __shfl_xor_sync(0xffffffffu, mx1, 1));
        mx1 = fmaxf(mx1, __shfl_xor_sync(0xffffffffu, mx1, 2));

        const float mn0 = fmaxf(m0, mx0);
        const float mn1 = fmaxf(m1, mx1);
        const float corr0 = __expf(m0 - mn0);
        const float corr1 = __expf(m1 - mn1);
        m0 = mn0; m1 = mn1;

        float rs0 = 0.f, rs1 = 0.f;
        #pragma unroll
        for (int nf = 0; nf < 8; nf++) {
            const float p0 = __expf(s[nf][0] - mn0);
            const float p1 = __expf(s[nf][1] - mn0);
            const float p2 = __expf(s[nf][2] - mn1);
            const float p3 = __expf(s[nf][3] - mn1);
            rs0 += p0 + p1;
            rs1 += p2 + p3;
            float2 w0; w0.x = p0; w0.y = p1;
            float2 w1; w1.x = p2; w1.y = p3;
            *(float2*)&ps[(wband + g    )*FPT + nf*8 + 2*tig] = w0;
            *(float2*)&ps[(wband + g + 8)*FPT + nf*8 + 2*tig] = w1;
        }
        rs0 += __shfl_xor_sync(0xffffffffu, rs0, 1);
        rs0 += __shfl_xor_sync(0xffffffffu, rs0, 2);
        rs1 += __shfl_xor_sync(0xffffffffu, rs1, 1);
        rs1 += __shfl_xor_sync(0xffffffffu, rs1, 2);
        l0 = l0 * corr0 + rs0;
        l1 = l1 * corr1 + rs1;

        #pragma unroll
        for (int nf = 0; nf < 8; nf++) {
            o[nf][0] *= corr0; o[nf][1] *= corr0;
            o[nf][2] *= corr1; o[nf][3] *= corr1;
        }
        __syncwarp();

        // O += P @ V
        #pragma unroll
        for (int kf = 0; kf < 8; kf++) {
            uint32_t pa[4];
            pa[0] = f2tf(ps[(wband + g    )*FPT + kf*8 + tig]);
            pa[1] = f2tf(ps[(wband + g + 8)*FPT + kf*8 + tig]);
            pa[2] = f2tf(ps[(wband + g    )*FPT + kf*8 + tig + 4]);
            pa[3] = f2tf(ps[(wband + g + 8)*FPT + kf*8 + tig + 4]);
            #pragma unroll
            for (int nf = 0; nf < 8; nf++) {
                uint32_t bv[2];
                bv[0] = Vt[(nf*8 + g)*FPT + kf*8 + tig];
                bv[1] = Vt[(nf*8 + g)*FPT + kf*8 + tig + 4];
                mma8(o[nf], pa, bv);
            }
        }
        __syncwarp();  // ps reads done before next iter overwrites
    }

    // epilogue: O / l  -> g_ao [B,N,C], c = h*64 + d
    const float inv0 = 1.0f / l0;
    const float inv1 = 1.0f / l1;
    const int n0 = qtile*64 + wband + g;
    const int n1 = n0 + 8;
    #pragma unroll
    for (int nf = 0; nf < 8; nf++) {
        const int d = h*64 + nf*8 + 2*tig;
        float2 w0; w0.x = o[nf][0]*inv0; w0.y = o[nf][1]*inv0;
        float2 w1; w1.x = o[nf][2]*inv1; w1.y = o[nf][3]*inv1;
        *(float2*)&g_ao[((size_t)b*N_ + n0)*C_ + d] = w0;
        *(float2*)&g_ao[((size_t)b*N_ + n1)*C_ + d] = w1;
    }
}

// ---------------------------------------------------------------------------
extern "C" void kernel_launch(void* const* d_in, const int* in_sizes, int n_in,
                              void* d_out, int out_size)
{
    const float* x     = (const float*)d_in[0];   // [B,N,C]
    const float* wqkv  = (const float*)d_in[1];   // [3C,C]
    const float* wproj = (const float*)d_in[2];   // [C,C]
    float* out = (float*)d_out;                   // [B,N,C]

    // 1) QKV GEMM -> q/k/v [B,H,N,D]
    {
        dim3 grid(3*C_/128, (B_*N_)/128);   // (18, 64)
        gemm_tf32<0><<<grid, 256>>>(x, wqkv, nullptr, B_*N_, 3*C_, C_);
    }

    // 2) LayerNorm on q (*SCALE) and k
    {
        const int warps = 2 * BH_ * N_;
        const int blocks = (warps * 32 + 255) / 256;
        ln_kernel<<<blocks, 256>>>();
    }

    // 3) Flash attention -> g_ao
    {
        const int smem_bytes = (2*64*FPT)*(int)sizeof(uint32_t)
                             + (64*FPT)*(int)sizeof(float);   // 52224
        cudaFuncSetAttribute(flash_tf32,
                             cudaFuncAttributeMaxDynamicSharedMemorySize, smem_bytes);
        dim3 grid(N_/64, BH_);   // (16, 96)
        flash_tf32<<<grid, 128, smem_bytes>>>();
    }

    // 4) Output projection
    {
        dim3 grid(C_/128, (B_*N_)/128);     // (6, 64)
        gemm_tf32<1><<<grid, 256>>>(nullptr, wproj, out, B_*N_, C_, C_);
    }
}